// round 7
// baseline (speedup 1.0000x reference)
#include <cuda_runtime.h>
#include <cstdint>

#define NT 512
#define SST 132            // sAct row stride (floats)
#define HST 68             // sHead row stride
#define BTOT 16384

// ---- dynamic smem layout (float offsets) ----
#define F_ACT   0                        // sAct[128][SST]
#define F_W1    (F_ACT + 128*SST)        // 16384 (blocked K8=16)
#define F_WUL   (F_W1 + 16384)           // 4096  (blocked K8=8)
#define F_W2    (F_WUL + 4096)           // 8192  (blocked K8=16)
#define F_HEAD  (F_W2 + 8192)            // sHead[128][HST]
#define F_WV    (F_HEAD + 128*HST)       // 256: w_vv|w_ev|w_ve|w_ee
#define F_BUL   (F_WV + 256)             // 64
#define F_B1    (F_BUL + 64)             // 128
#define F_B2    (F_B1 + 128)             // 64
#define F_W3    (F_B2 + 64)              // 64
#define F_OUT   (F_W3 + 64)              // 128 (output accumulator)
#define SMEM_FLOATS (F_OUT + 128)
#define SMEM_BYTES  (SMEM_FLOATS * 4 + 128)

__device__ __forceinline__ uint32_t smem_u32(const void* p) {
    uint32_t a;
    asm("{ .reg .u64 t; cvta.to.shared.u64 t, %1; cvt.u32.u64 %0, t; }" : "=r"(a) : "l"(p));
    return a;
}
__device__ __forceinline__ void ldsm4(uint32_t* r, uint32_t addr) {
    asm volatile("ldmatrix.sync.aligned.m8n8.x4.shared.b16 {%0,%1,%2,%3}, [%4];"
                 : "=r"(r[0]), "=r"(r[1]), "=r"(r[2]), "=r"(r[3]) : "r"(addr));
}
__device__ __forceinline__ void mma8(float* c, const uint32_t* a, const uint32_t* b) {
    asm("mma.sync.aligned.m16n8k8.row.col.f32.tf32.tf32.f32 "
        "{%0,%1,%2,%3},{%4,%5,%6,%7},{%8,%9},{%0,%1,%2,%3};"
        : "+f"(c[0]), "+f"(c[1]), "+f"(c[2]), "+f"(c[3])
        : "r"(a[0]), "r"(a[1]), "r"(a[2]), "r"(a[3]), "r"(b[0]), "r"(b[1]));
}
// blocked B layout: float index of element (n,k); K8 = K/8
__device__ __forceinline__ int bwoff(int n, int k, int K8) {
    return (((n >> 3) * K8 + (k >> 3)) << 6) + (((k >> 2) & 1) << 5) + ((n & 7) << 2) + (k & 3);
}
__device__ __forceinline__ void cpa16(uint32_t dst, const void* src) {
    asm volatile("cp.async.cg.shared.global [%0], [%1], 16;" :: "r"(dst), "l"(src));
}
__device__ __forceinline__ void cpa4(uint32_t dst, const void* src) {
    asm volatile("cp.async.ca.shared.global [%0], [%1], 4;" :: "r"(dst), "l"(src));
}
#define CP_COMMIT() asm volatile("cp.async.commit_group;" ::: "memory")
#define CP_WAIT(n)  asm volatile("cp.async.wait_group %0;" :: "n"(n) : "memory")
#define BAR_U() asm volatile("bar.sync 1, 256;" ::: "memory")
#define BAR_C() asm volatile("bar.sync 2, 256;" ::: "memory")

__global__ __launch_bounds__(NT, 1)
void multikr_mma_kernel(const int* __restrict__ user_id,
                        const int* __restrict__ item_id,
                        const float* __restrict__ rec_target,
                        const float* __restrict__ user_emb,
                        const float* __restrict__ item_emb,
                        const float* __restrict__ entity_emb,
                        const float* __restrict__ w_vv,
                        const float* __restrict__ w_ev,
                        const float* __restrict__ w_ve,
                        const float* __restrict__ w_ee,
                        const float* __restrict__ b_v,
                        const float* __restrict__ b_e,
                        const float* __restrict__ Wul,
                        const float* __restrict__ bul,
                        const float* __restrict__ W1,
                        const float* __restrict__ b1,
                        const float* __restrict__ W2,
                        const float* __restrict__ b2,
                        const float* __restrict__ W3,
                        const float* __restrict__ b3,
                        float* __restrict__ out,
                        int out_size)
{
    extern __shared__ float sm[];
    float* sAct  = sm + F_ACT;
    float* sHead = sm + F_HEAD;
    float* sWV   = sm + F_WV;
    float* sBUL  = sm + F_BUL;
    float* sB1   = sm + F_B1;
    float* sB2   = sm + F_B2;
    float* sW3   = sm + F_W3;
    float* sOut  = sm + F_OUT;

    const int t    = threadIdx.x;
    const int l    = t & 31;
    const int wid  = t >> 5;
    const int mtx  = l >> 3, p = l & 7;
    const int base = blockIdx.x * 128;

    const uint32_t uAct  = smem_u32(sAct);
    const uint32_t uW1s  = smem_u32(sm + F_W1);
    const uint32_t uWuls = smem_u32(sm + F_WUL);
    const uint32_t uW2s  = smem_u32(sm + F_W2);
    const uint32_t uHead = smem_u32(sHead);
    const uint32_t uWVs  = smem_u32(sWV);
    const uint32_t uBULs = smem_u32(sBUL);
    const uint32_t uB1s  = smem_u32(sB1);
    const uint32_t uB2s  = smem_u32(sB2);
    const uint32_t uW3s  = smem_u32(sW3);

    // per-thread ldmatrix offsets (bytes)
    const uint32_t aoffT   = 4u * (((mtx & 1) * 8 + p) * SST + (mtx >> 1) * 4);
    const uint32_t boffT8  = 4u * (((mtx >> 1) * 8  << 6) + ((mtx & 1) << 5) + (p << 2));
    const uint32_t boffT16 = 4u * (((mtx >> 1) * 16 << 6) + ((mtx & 1) << 5) + (p << 2));

    // ============ async front-end: 4 commit groups (content split by role) ============
    if (t < 256) {
        // G0 (user half): Wul blocked + user gather + bul
        #pragma unroll
        for (int i = 0; i < 16; i++) {
            int idx = t + i * 256;
            cpa4(uWuls + 4u * bwoff(idx & 63, idx >> 6, 8), Wul + (idx >> 6) * 64 + (idx & 63));
        }
        #pragma unroll
        for (int i = 0; i < 8; i++) {
            int cid = t + i * 256;
            int s = cid >> 4, j = cid & 15;
            int uid = __ldg(user_id + base + s);
            cpa16(uAct + 4u * (s * SST + j * 4), user_emb + (size_t)uid * 64 + j * 4);
        }
        if (t < 64) cpa4(uBULs + 4u * t, bul + t);
        CP_COMMIT();
        CP_COMMIT();    // empty G1
    } else {
        const int ct = t - 256;
        // G0 (cross half): WV + b1/b2/w3
        if (ct < 128) {
            const float* w1p = (ct < 64) ? (w_vv + ct) : (w_ev + ct - 64);
            const float* w2p = (ct < 64) ? (w_ve + ct) : (w_ee + ct - 64);
            cpa4(uWVs + 4u * ct, w1p);
            cpa4(uWVs + 4u * (128 + ct), w2p);
            cpa4(uB1s + 4u * ct, b1 + ct);
            if (ct < 64) { cpa4(uB2s + 4u * ct, b2 + ct); cpa4(uW3s + 4u * ct, W3 + ct); }
        }
        CP_COMMIT();
        // G1: item + head gathers
        #pragma unroll
        for (int i = 0; i < 8; i++) {
            int cid = ct + i * 256;
            int s = cid >> 4, j = cid & 15;
            int iid = __ldg(item_id + base + s);
            cpa16(uAct + 4u * (s * SST + 64 + j * 4), item_emb + (size_t)iid * 64 + j * 4);
            cpa16(uHead + 4u * (s * HST + j * 4), entity_emb + (size_t)iid * 64 + j * 4);
        }
        CP_COMMIT();
    }
    // G2: W1 (all threads)
    #pragma unroll 8
    for (int i = 0; i < 32; i++) {
        int idx = t + i * 512;
        cpa4(uW1s + 4u * bwoff(idx & 127, idx >> 7, 16), W1 + (idx >> 7) * 128 + (idx & 127));
    }
    CP_COMMIT();
    // G3: W2 (all threads)
    #pragma unroll 8
    for (int i = 0; i < 16; i++) {
        int idx = t + i * 512;
        cpa4(uW2s + 4u * bwoff(idx & 63, idx >> 6, 16), W2 + (idx >> 6) * 64 + (idx & 63));
    }
    CP_COMMIT();

    // rec_target passthrough (cross half threads 384-511; overlaps cp.async)
    if (t >= 384 && out_size >= 2 * BTOT)
        out[BTOT + base + (t - 384)] = __ldg(rec_target + base + (t - 384));

    // ============ phase 1: user MLP chain (warps 0-7) || cross chain (warps 8-15) ============
    if (t < 256) {
        const int wm = wid & 1, wn = wid >> 1;     // M half (64 rows), N quarter (16 cols)
        CP_WAIT(3);
        BAR_U();                                   // Wul + user + bul visible
        #pragma unroll 1
        for (int layer = 0; layer < 2; layer++) {
            float acc[4][2][4];
            #pragma unroll
            for (int mt = 0; mt < 4; mt++)
                #pragma unroll
                for (int nt = 0; nt < 2; nt++)
                    #pragma unroll
                    for (int i = 0; i < 4; i++) acc[mt][nt][i] = 0.f;
            const int nb0 = wn * 2;
            #pragma unroll
            for (int k8 = 0; k8 < 8; k8++) {
                uint32_t a[4][4], b[4];
                #pragma unroll
                for (int mt = 0; mt < 4; mt++)
                    ldsm4(a[mt], uAct + 4u * ((wm * 64 + mt * 16) * SST + k8 * 8) + aoffT);
                ldsm4(b, uWuls + 4u * ((nb0 * 8 + k8) << 6) + boffT8);
                #pragma unroll
                for (int mt = 0; mt < 4; mt++) {
                    mma8(acc[mt][0], a[mt], b);
                    mma8(acc[mt][1], a[mt], b + 2);
                }
            }
            BAR_U();     // all user-half reads of cols 0-63 done
            const int r0b = wm * 64 + (l >> 2);
            const int cb  = wn * 16 + 2 * (l & 3);
            #pragma unroll
            for (int mt = 0; mt < 4; mt++)
                #pragma unroll
                for (int nt = 0; nt < 2; nt++) {
                    int c = cb + nt * 8;
                    float bb0 = sBUL[c], bb1 = sBUL[c + 1];
                    int r0 = r0b + mt * 16;
                    float2 v0, v1;
                    v0.x = fmaxf(acc[mt][nt][0] + bb0, 0.f);
                    v0.y = fmaxf(acc[mt][nt][1] + bb1, 0.f);
                    v1.x = fmaxf(acc[mt][nt][2] + bb0, 0.f);
                    v1.y = fmaxf(acc[mt][nt][3] + bb1, 0.f);
                    *(float2*)&sAct[r0 * SST + c] = v0;
                    *(float2*)&sAct[(r0 + 8) * SST + c] = v1;
                }
            BAR_U();     // epilogue writes visible before next layer reads
        }
        if (t < 128) sOut[t] = 0.f;   // zero output accumulator
    } else {
        const int tc = t - 256;                    // 2 threads per sample
        const int s  = tc >> 1, kh = tc & 1;
        const float bvv = __ldg(b_v), bee = __ldg(b_e);
        CP_WAIT(2);
        BAR_C();                                   // WV + item + head visible
        float* itp = &sAct[s * SST + 64 + kh * 32];
        float* hdp = &sHead[s * HST + kh * 32];
        const float* wv0 = &sWV[kh * 32];
        #pragma unroll 1
        for (int layer = 0; layer < 2; layer++) {
            float s1 = 0.f, s2 = 0.f, s3 = 0.f, s4 = 0.f;
            #pragma unroll
            for (int j = 0; j < 8; j++) {
                float4 iv = *(const float4*)&itp[j * 4];
                float4 hv = *(const float4*)&hdp[j * 4];
                float4 wvv = *(const float4*)&wv0[j * 4];
                float4 wev = *(const float4*)&wv0[64 + j * 4];
                s1 = fmaf(hv.x, wvv.x, fmaf(hv.y, wvv.y, fmaf(hv.z, wvv.z, fmaf(hv.w, wvv.w, s1))));
                s2 = fmaf(iv.x, wev.x, fmaf(iv.y, wev.y, fmaf(iv.z, wev.z, fmaf(iv.w, wev.w, s2))));
                if (layer == 0) {
                    float4 wve = *(const float4*)&wv0[128 + j * 4];
                    float4 wee = *(const float4*)&wv0[192 + j * 4];
                    s3 = fmaf(hv.x, wve.x, fmaf(hv.y, wve.y, fmaf(hv.z, wve.z, fmaf(hv.w, wve.w, s3))));
                    s4 = fmaf(iv.x, wee.x, fmaf(iv.y, wee.y, fmaf(iv.z, wee.z, fmaf(iv.w, wee.w, s4))));
                }
            }
            s1 += __shfl_xor_sync(0xffffffffu, s1, 1);
            s2 += __shfl_xor_sync(0xffffffffu, s2, 1);
            if (layer == 0) {
                s3 += __shfl_xor_sync(0xffffffffu, s3, 1);
                s4 += __shfl_xor_sync(0xffffffffu, s4, 1);
            }
            #pragma unroll
            for (int j = 0; j < 8; j++) {
                float4 iv = *(const float4*)&itp[j * 4];
                float4 hv = *(const float4*)&hdp[j * 4];
                float4 ni;
                ni.x = fmaf(iv.x, s1, fmaf(hv.x, s2, bvv));
                ni.y = fmaf(iv.y, s1, fmaf(hv.y, s2, bvv));
                ni.z = fmaf(iv.z, s1, fmaf(hv.z, s2, bvv));
                ni.w = fmaf(iv.w, s1, fmaf(hv.w, s2, bvv));
                *(float4*)&itp[j * 4] = ni;
                if (layer == 0) {    // head update dead after last layer
                    float4 nh;
                    nh.x = fmaf(iv.x, s3, fmaf(hv.x, s4, bee));
                    nh.y = fmaf(iv.y, s3, fmaf(hv.y, s4, bee));
                    nh.z = fmaf(iv.z, s3, fmaf(hv.z, s4, bee));
                    nh.w = fmaf(iv.w, s3, fmaf(hv.w, s4, bee));
                    *(float4*)&hdp[j * 4] = nh;
                }
            }
        }
    }

    CP_WAIT(1);          // W1 landed
    __syncthreads();     // concat point: user cols + item cols + W1 all visible

    // ============ GEMM1: M=128, N=128, K=128; 16 warps = 4M x 4N (32x32 tiles) ============
    const int wm2 = wid & 3, wn2 = wid >> 2;
    {
        float acc[2][4][4];
        #pragma unroll
        for (int mt = 0; mt < 2; mt++)
            #pragma unroll
            for (int nt = 0; nt < 4; nt++)
                #pragma unroll
                for (int i = 0; i < 4; i++) acc[mt][nt][i] = 0.f;
        const int nb0 = wn2 * 4;
        #pragma unroll
        for (int k8 = 0; k8 < 16; k8++) {
            uint32_t a[2][4], b[8];
            #pragma unroll
            for (int mt = 0; mt < 2; mt++)
                ldsm4(a[mt], uAct + 4u * ((wm2 * 32 + mt * 16) * SST + k8 * 8) + aoffT);
            ldsm4(b,     uW1s + 4u * (((nb0 + 0) * 16 + k8) << 6) + boffT16);
            ldsm4(b + 4, uW1s + 4u * (((nb0 + 2) * 16 + k8) << 6) + boffT16);
            #pragma unroll
            for (int mt = 0; mt < 2; mt++) {
                mma8(acc[mt][0], a[mt], b);
                mma8(acc[mt][1], a[mt], b + 2);
                mma8(acc[mt][2], a[mt], b + 4);
                mma8(acc[mt][3], a[mt], b + 6);
            }
        }
        __syncthreads();    // all reads done before h1 overwrites sAct
        const int r0b = wm2 * 32 + (l >> 2);
        const int cb  = wn2 * 32 + 2 * (l & 3);
        #pragma unroll
        for (int mt = 0; mt < 2; mt++)
            #pragma unroll
            for (int nt = 0; nt < 4; nt++) {
                int c = cb + nt * 8;
                float bb0 = sB1[c], bb1 = sB1[c + 1];
                int r0 = r0b + mt * 16;
                float2 v0, v1;
                v0.x = fmaxf(acc[mt][nt][0] + bb0, 0.f);
                v0.y = fmaxf(acc[mt][nt][1] + bb1, 0.f);
                v1.x = fmaxf(acc[mt][nt][2] + bb0, 0.f);
                v1.y = fmaxf(acc[mt][nt][3] + bb1, 0.f);
                *(float2*)&sAct[r0 * SST + c] = v0;
                *(float2*)&sAct[(r0 + 8) * SST + c] = v1;
            }
    }
    CP_WAIT(0);          // W2 landed
    __syncthreads();     // h1 visible

    // ============ GEMM2 (M=128, N=64; 4M x 4N of 16) + fused final 64->1 ============
    {
        float acc[2][2][4];
        #pragma unroll
        for (int mt = 0; mt < 2; mt++)
            #pragma unroll
            for (int nt = 0; nt < 2; nt++)
                #pragma unroll
                for (int i = 0; i < 4; i++) acc[mt][nt][i] = 0.f;
        const int nb0 = wn2 * 2;
        #pragma unroll
        for (int k8 = 0; k8 < 16; k8++) {
            uint32_t a[2][4], b[4];
            #pragma unroll
            for (int mt = 0; mt < 2; mt++)
                ldsm4(a[mt], uAct + 4u * ((wm2 * 32 + mt * 16) * SST + k8 * 8) + aoffT);
            ldsm4(b, uW2s + 4u * ((nb0 * 16 + k8) << 6) + boffT16);
            #pragma unroll
            for (int mt = 0; mt < 2; mt++) {
                mma8(acc[mt][0], a[mt], b);
                mma8(acc[mt][1], a[mt], b + 2);
            }
        }
        // fused: p[row] += relu(h2+b2)*w3, reduce over lane column-group, atomic into sOut
        const int cb = wn2 * 16 + 2 * (l & 3);
        float part[2][2];
        #pragma unroll
        for (int mt = 0; mt < 2; mt++) { part[mt][0] = 0.f; part[mt][1] = 0.f; }
        #pragma unroll
        for (int nt = 0; nt < 2; nt++) {
            int c = cb + nt * 8;
            float bb0 = sB2[c], bb1 = sB2[c + 1];
            float w30 = sW3[c], w31 = sW3[c + 1];
            #pragma unroll
            for (int mt = 0; mt < 2; mt++) {
                part[mt][0] = fmaf(fmaxf(acc[mt][nt][0] + bb0, 0.f), w30,
                              fmaf(fmaxf(acc[mt][nt][1] + bb1, 0.f), w31, part[mt][0]));
                part[mt][1] = fmaf(fmaxf(acc[mt][nt][2] + bb0, 0.f), w30,
                              fmaf(fmaxf(acc[mt][nt][3] + bb1, 0.f), w31, part[mt][1]));
            }
        }
        #pragma unroll
        for (int mt = 0; mt < 2; mt++)
            #pragma unroll
            for (int rh = 0; rh < 2; rh++) {
                part[mt][rh] += __shfl_xor_sync(0xffffffffu, part[mt][rh], 1);
                part[mt][rh] += __shfl_xor_sync(0xffffffffu, part[mt][rh], 2);
            }
        if ((l & 3) == 0) {
            const int r0b = wm2 * 32 + (l >> 2);
            #pragma unroll
            for (int mt = 0; mt < 2; mt++) {
                atomicAdd(&sOut[r0b + mt * 16],     part[mt][0]);
                atomicAdd(&sOut[r0b + mt * 16 + 8], part[mt][1]);
            }
        }
    }
    __syncthreads();

    // ============ output ============
    if (t < 128)
        out[base + t] = fmaxf(sOut[t] + __ldg(b3), 0.f);
}

extern "C" void kernel_launch(void* const* d_in, const int* in_sizes, int n_in,
                              void* d_out, int out_size)
{
    const int*   user_id    = (const int*)d_in[0];
    const int*   item_id    = (const int*)d_in[1];
    const float* rec_target = (const float*)d_in[2];
    const float* user_emb   = (const float*)d_in[3];
    const float* item_emb   = (const float*)d_in[4];
    const float* entity_emb = (const float*)d_in[5];
    const float* w_vv = (const float*)d_in[6];
    const float* w_ev = (const float*)d_in[7];
    const float* w_ve = (const float*)d_in[8];
    const float* w_ee = (const float*)d_in[9];
    const float* b_v  = (const float*)d_in[10];
    const float* b_e  = (const float*)d_in[11];
    const float* Wul  = (const float*)d_in[12];
    const float* bul  = (const float*)d_in[13];
    const float* W1   = (const float*)d_in[14];
    const float* b1   = (const float*)d_in[15];
    const float* W2   = (const float*)d_in[16];
    const float* b2   = (const float*)d_in[17];
    const float* W3   = (const float*)d_in[18];
    const float* b3   = (const float*)d_in[19];

    cudaFuncSetAttribute(multikr_mma_kernel,
                         cudaFuncAttributeMaxDynamicSharedMemorySize, SMEM_BYTES);

    const int n = in_sizes[0];      // 16384
    const int nblk = n / 128;       // 128 blocks, one wave
    multikr_mma_kernel<<<nblk, NT, SMEM_BYTES>>>(
        user_id, item_id, rec_target, user_emb, item_emb, entity_emb,
        w_vv, w_ev, w_ve, w_ee, b_v, b_e, Wul, bul,
        W1, b1, W2, b2, W3, b3,
        (float*)d_out, out_size);
}

// round 8
// speedup vs baseline: 1.2045x; 1.2045x over previous
#include <cuda_runtime.h>
#include <cstdint>

#define NT 256
#define SST 132            // sAct row stride (floats); 528B = 16 mod 128 -> ldsm conflict-free
#define HST 68             // sHead / ping row stride; 272B = 16 mod 128 -> conflict-free
#define BTOT 16384

// ---- dynamic smem layout (float offsets) ----
#define F_ACT   0                        // sAct[128][SST] = 16896
#define F_W1    (F_ACT + 128*SST)        // 16384 (blocked K8=16)
#define F_WUL   (F_W1 + 16384)           // 4096  (blocked K8=8)
#define F_HEAD  (F_WUL + 4096)           // sHead[128][HST] = 8704
#define F_PING  (F_HEAD + 8704)          // 8704: phase1 = user ping [128][HST]; later W2 blocked (8192)
#define F_WV    (F_PING + 8704)          // 256: w_vv|w_ev|w_ve|w_ee
#define F_BUL   (F_WV + 256)             // 64
#define F_B1    (F_BUL + 64)             // 128
#define F_B2    (F_B1 + 128)             // 64
#define F_W3    (F_B2 + 64)              // 64
#define F_OUT   (F_W3 + 64)              // 128 (output accumulator)
#define SMEM_FLOATS (F_OUT + 128)
#define SMEM_BYTES  (SMEM_FLOATS * 4 + 128)

__device__ __forceinline__ uint32_t smem_u32(const void* p) {
    uint32_t a;
    asm("{ .reg .u64 t; cvta.to.shared.u64 t, %1; cvt.u32.u64 %0, t; }" : "=r"(a) : "l"(p));
    return a;
}
__device__ __forceinline__ void ldsm4(uint32_t* r, uint32_t addr) {
    asm volatile("ldmatrix.sync.aligned.m8n8.x4.shared.b16 {%0,%1,%2,%3}, [%4];"
                 : "=r"(r[0]), "=r"(r[1]), "=r"(r[2]), "=r"(r[3]) : "r"(addr));
}
__device__ __forceinline__ void mma8(float* c, const uint32_t* a, const uint32_t* b) {
    asm("mma.sync.aligned.m16n8k8.row.col.f32.tf32.tf32.f32 "
        "{%0,%1,%2,%3},{%4,%5,%6,%7},{%8,%9},{%0,%1,%2,%3};"
        : "+f"(c[0]), "+f"(c[1]), "+f"(c[2]), "+f"(c[3])
        : "r"(a[0]), "r"(a[1]), "r"(a[2]), "r"(a[3]), "r"(b[0]), "r"(b[1]));
}
// blocked B layout: float index of element (n,k); K8 = K/8
__device__ __forceinline__ int bwoff(int n, int k, int K8) {
    return (((n >> 3) * K8 + (k >> 3)) << 6) + (((k >> 2) & 1) << 5) + ((n & 7) << 2) + (k & 3);
}
__device__ __forceinline__ void cpa16(uint32_t dst, const void* src) {
    asm volatile("cp.async.cg.shared.global [%0], [%1], 16;" :: "r"(dst), "l"(src));
}
__device__ __forceinline__ void cpa4(uint32_t dst, const void* src) {
    asm volatile("cp.async.ca.shared.global [%0], [%1], 4;" :: "r"(dst), "l"(src));
}
#define CP_COMMIT() asm volatile("cp.async.commit_group;" ::: "memory")
#define CP_WAIT(n)  asm volatile("cp.async.wait_group %0;" :: "n"(n) : "memory")
#define BAR_U() asm volatile("bar.sync 1, 128;" ::: "memory")
#define BAR_C() asm volatile("bar.sync 2, 128;" ::: "memory")

__global__ __launch_bounds__(NT, 1)
void multikr_mma_kernel(const int* __restrict__ user_id,
                        const int* __restrict__ item_id,
                        const float* __restrict__ rec_target,
                        const float* __restrict__ user_emb,
                        const float* __restrict__ item_emb,
                        const float* __restrict__ entity_emb,
                        const float* __restrict__ w_vv,
                        const float* __restrict__ w_ev,
                        const float* __restrict__ w_ve,
                        const float* __restrict__ w_ee,
                        const float* __restrict__ b_v,
                        const float* __restrict__ b_e,
                        const float* __restrict__ Wul,
                        const float* __restrict__ bul,
                        const float* __restrict__ W1,
                        const float* __restrict__ b1,
                        const float* __restrict__ W2,
                        const float* __restrict__ b2,
                        const float* __restrict__ W3,
                        const float* __restrict__ b3,
                        float* __restrict__ out,
                        int out_size)
{
    extern __shared__ float sm[];
    float* sAct  = sm + F_ACT;
    float* sHead = sm + F_HEAD;
    float* sPing = sm + F_PING;
    float* sWV   = sm + F_WV;
    float* sBUL  = sm + F_BUL;
    float* sB1   = sm + F_B1;
    float* sB2   = sm + F_B2;
    float* sW3   = sm + F_W3;
    float* sOut  = sm + F_OUT;

    const int t    = threadIdx.x;
    const int l    = t & 31;
    const int wid  = t >> 5;
    const int mtx  = l >> 3, p = l & 7;
    const int base = blockIdx.x * 128;

    const uint32_t uAct  = smem_u32(sAct);
    const uint32_t uW1s  = smem_u32(sm + F_W1);
    const uint32_t uWuls = smem_u32(sm + F_WUL);
    const uint32_t uPing = smem_u32(sPing);      // doubles as W2 region later
    const uint32_t uHead = smem_u32(sHead);
    const uint32_t uWVs  = smem_u32(sWV);
    const uint32_t uBULs = smem_u32(sBUL);
    const uint32_t uB1s  = smem_u32(sB1);
    const uint32_t uB2s  = smem_u32(sB2);
    const uint32_t uW3s  = smem_u32(sW3);

    // per-thread ldmatrix offsets (bytes)
    const uint32_t aoffT   = 4u * (((mtx & 1) * 8 + p) * SST + (mtx >> 1) * 4);
    const uint32_t aoffP   = 4u * (((mtx & 1) * 8 + p) * HST + (mtx >> 1) * 4);
    const uint32_t boffT8  = 4u * (((mtx >> 1) * 8  << 6) + ((mtx & 1) << 5) + (p << 2));
    const uint32_t boffT16 = 4u * (((mtx >> 1) * 16 << 6) + ((mtx & 1) << 5) + (p << 2));

    // ============ async front-end (W2 deferred; its region is the phase-1 ping buffer) ============
    if (t < 128) {
        // G0 (user warps): Wul blocked + user gather + bul
        #pragma unroll
        for (int i = 0; i < 32; i++) {
            int idx = t + i * 128;
            cpa4(uWuls + 4u * bwoff(idx & 63, idx >> 6, 8), Wul + (idx >> 6) * 64 + (idx & 63));
        }
        #pragma unroll
        for (int i = 0; i < 16; i++) {
            int cid = t + i * 128;
            int s = cid >> 4, j = cid & 15;
            int uid = __ldg(user_id + base + s);
            cpa16(uAct + 4u * (s * SST + j * 4), user_emb + (size_t)uid * 64 + j * 4);
        }
        if (t < 64) cpa4(uBULs + 4u * t, bul + t);
        CP_COMMIT();
        CP_COMMIT();    // empty G1
    } else {
        const int ct = t - 128;
        // G0 (cross warps): WV + b1/b2/w3
        {
            const float* w1p = (ct < 64) ? (w_vv + ct) : (w_ev + ct - 64);
            const float* w2p = (ct < 64) ? (w_ve + ct) : (w_ee + ct - 64);
            cpa4(uWVs + 4u * ct, w1p);
            cpa4(uWVs + 4u * (128 + ct), w2p);
            cpa4(uB1s + 4u * ct, b1 + ct);
            if (ct < 64) { cpa4(uB2s + 4u * ct, b2 + ct); cpa4(uW3s + 4u * ct, W3 + ct); }
        }
        CP_COMMIT();
        // G1: item + head gathers
        #pragma unroll
        for (int i = 0; i < 16; i++) {
            int cid = ct + i * 128;
            int s = cid >> 4, j = cid & 15;
            int iid = __ldg(item_id + base + s);
            cpa16(uAct + 4u * (s * SST + 64 + j * 4), item_emb + (size_t)iid * 64 + j * 4);
            cpa16(uHead + 4u * (s * HST + j * 4), entity_emb + (size_t)iid * 64 + j * 4);
        }
        CP_COMMIT();
    }
    // G2: W1 (all threads)
    #pragma unroll 8
    for (int i = 0; i < 64; i++) {
        int idx = t + i * 256;
        cpa4(uW1s + 4u * bwoff(idx & 127, idx >> 7, 16), W1 + (idx >> 7) * 128 + (idx & 127));
    }
    CP_COMMIT();

    // rec_target passthrough (independent; overlaps cp.async)
    if (t >= 128 && out_size >= 2 * BTOT)
        out[BTOT + base + (t - 128)] = __ldg(rec_target + base + (t - 128));

    // ============ phase 1: user MLP chain (warps 0-3) || cross chain (warps 4-7) ============
    if (t < 128) {
        const int wm = wid & 1, wn = wid >> 1;     // M half (64 rows), N half (32 cols)
        const int nb0 = wn * 4;
        CP_WAIT(2);                                // G0 (Wul+user+bul) landed
        BAR_U();
        sOut[t] = 0.f;                             // zero output accumulator

        // ---- layer 1: read sAct cols 0-63, write ping (no WAR barrier needed) ----
        {
            float acc[4][4][4];
            #pragma unroll
            for (int mt = 0; mt < 4; mt++)
                #pragma unroll
                for (int nt = 0; nt < 4; nt++)
                    #pragma unroll
                    for (int i = 0; i < 4; i++) acc[mt][nt][i] = 0.f;
            uint32_t a[2][4][4], b[2][8];
            #pragma unroll
            for (int mt = 0; mt < 4; mt++)
                ldsm4(a[0][mt], uAct + 4u * ((wm * 64 + mt * 16) * SST) + aoffT);
            ldsm4(b[0],     uWuls + 4u * (((nb0 + 0) * 8) << 6) + boffT8);
            ldsm4(b[0] + 4, uWuls + 4u * (((nb0 + 2) * 8) << 6) + boffT8);
            #pragma unroll
            for (int k8 = 0; k8 < 8; k8++) {
                const int cur = k8 & 1, nxt = cur ^ 1;
                if (k8 < 7) {
                    #pragma unroll
                    for (int mt = 0; mt < 4; mt++)
                        ldsm4(a[nxt][mt], uAct + 4u * ((wm * 64 + mt * 16) * SST + (k8 + 1) * 8) + aoffT);
                    ldsm4(b[nxt],     uWuls + 4u * (((nb0 + 0) * 8 + k8 + 1) << 6) + boffT8);
                    ldsm4(b[nxt] + 4, uWuls + 4u * (((nb0 + 2) * 8 + k8 + 1) << 6) + boffT8);
                }
                #pragma unroll
                for (int mt = 0; mt < 4; mt++) {
                    mma8(acc[mt][0], a[cur][mt], b[cur]);
                    mma8(acc[mt][1], a[cur][mt], b[cur] + 2);
                    mma8(acc[mt][2], a[cur][mt], b[cur] + 4);
                    mma8(acc[mt][3], a[cur][mt], b[cur] + 6);
                }
            }
            const int r0b = wm * 64 + (l >> 2);
            const int cb  = wn * 32 + 2 * (l & 3);
            #pragma unroll
            for (int mt = 0; mt < 4; mt++)
                #pragma unroll
                for (int nt = 0; nt < 4; nt++) {
                    int c = cb + nt * 8;
                    float bb0 = sBUL[c], bb1 = sBUL[c + 1];
                    int r0 = r0b + mt * 16;
                    float2 v0, v1;
                    v0.x = fmaxf(acc[mt][nt][0] + bb0, 0.f);
                    v0.y = fmaxf(acc[mt][nt][1] + bb1, 0.f);
                    v1.x = fmaxf(acc[mt][nt][2] + bb0, 0.f);
                    v1.y = fmaxf(acc[mt][nt][3] + bb1, 0.f);
                    *(float2*)&sPing[r0 * HST + c] = v0;
                    *(float2*)&sPing[(r0 + 8) * HST + c] = v1;
                }
        }
        BAR_U();    // ping visible to all user warps

        // ---- layer 2: read ping, write sAct cols 0-63 (no WAR barrier needed) ----
        {
            float acc[4][4][4];
            #pragma unroll
            for (int mt = 0; mt < 4; mt++)
                #pragma unroll
                for (int nt = 0; nt < 4; nt++)
                    #pragma unroll
                    for (int i = 0; i < 4; i++) acc[mt][nt][i] = 0.f;
            uint32_t a[2][4][4], b[2][8];
            #pragma unroll
            for (int mt = 0; mt < 4; mt++)
                ldsm4(a[0][mt], uPing + 4u * ((wm * 64 + mt * 16) * HST) + aoffP);
            ldsm4(b[0],     uWuls + 4u * (((nb0 + 0) * 8) << 6) + boffT8);
            ldsm4(b[0] + 4, uWuls + 4u * (((nb0 + 2) * 8) << 6) + boffT8);
            #pragma unroll
            for (int k8 = 0; k8 < 8; k8++) {
                const int cur = k8 & 1, nxt = cur ^ 1;
                if (k8 < 7) {
                    #pragma unroll
                    for (int mt = 0; mt < 4; mt++)
                        ldsm4(a[nxt][mt], uPing + 4u * ((wm * 64 + mt * 16) * HST + (k8 + 1) * 8) + aoffP);
                    ldsm4(b[nxt],     uWuls + 4u * (((nb0 + 0) * 8 + k8 + 1) << 6) + boffT8);
                    ldsm4(b[nxt] + 4, uWuls + 4u * (((nb0 + 2) * 8 + k8 + 1) << 6) + boffT8);
                }
                #pragma unroll
                for (int mt = 0; mt < 4; mt++) {
                    mma8(acc[mt][0], a[cur][mt], b[cur]);
                    mma8(acc[mt][1], a[cur][mt], b[cur] + 2);
                    mma8(acc[mt][2], a[cur][mt], b[cur] + 4);
                    mma8(acc[mt][3], a[cur][mt], b[cur] + 6);
                }
            }
            const int r0b = wm * 64 + (l >> 2);
            const int cb  = wn * 32 + 2 * (l & 3);
            #pragma unroll
            for (int mt = 0; mt < 4; mt++)
                #pragma unroll
                for (int nt = 0; nt < 4; nt++) {
                    int c = cb + nt * 8;
                    float bb0 = sBUL[c], bb1 = sBUL[c + 1];
                    int r0 = r0b + mt * 16;
                    float2 v0, v1;
                    v0.x = fmaxf(acc[mt][nt][0] + bb0, 0.f);
                    v0.y = fmaxf(acc[mt][nt][1] + bb1, 0.f);
                    v1.x = fmaxf(acc[mt][nt][2] + bb0, 0.f);
                    v1.y = fmaxf(acc[mt][nt][3] + bb1, 0.f);
                    *(float2*)&sAct[r0 * SST + c] = v0;
                    *(float2*)&sAct[(r0 + 8) * SST + c] = v1;
                }
        }
    } else {
        const int s = t - 128;                     // 1 thread per sample
        const float bvv = __ldg(b_v), bee = __ldg(b_e);
        CP_WAIT(1);                                // G0 + G1 landed
        BAR_C();
        float* itp = &sAct[s * SST + 64];
        float* hdp = &sHead[s * HST];
        #pragma unroll 1
        for (int layer = 0; layer < 2; layer++) {
            float s1 = 0.f, s2 = 0.f, s3 = 0.f, s4 = 0.f;
            #pragma unroll
            for (int j = 0; j < 16; j++) {
                float4 iv = *(const float4*)&itp[j * 4];
                float4 hv = *(const float4*)&hdp[j * 4];
                float4 wvv = *(const float4*)&sWV[j * 4];
                float4 wev = *(const float4*)&sWV[64 + j * 4];
                s1 = fmaf(hv.x, wvv.x, fmaf(hv.y, wvv.y, fmaf(hv.z, wvv.z, fmaf(hv.w, wvv.w, s1))));
                s2 = fmaf(iv.x, wev.x, fmaf(iv.y, wev.y, fmaf(iv.z, wev.z, fmaf(iv.w, wev.w, s2))));
                if (layer == 0) {
                    float4 wve = *(const float4*)&sWV[128 + j * 4];
                    float4 wee = *(const float4*)&sWV[192 + j * 4];
                    s3 = fmaf(hv.x, wve.x, fmaf(hv.y, wve.y, fmaf(hv.z, wve.z, fmaf(hv.w, wve.w, s3))));
                    s4 = fmaf(iv.x, wee.x, fmaf(iv.y, wee.y, fmaf(iv.z, wee.z, fmaf(iv.w, wee.w, s4))));
                }
            }
            #pragma unroll
            for (int j = 0; j < 16; j++) {
                float4 iv = *(const float4*)&itp[j * 4];
                float4 hv = *(const float4*)&hdp[j * 4];
                float4 ni;
                ni.x = fmaf(iv.x, s1, fmaf(hv.x, s2, bvv));
                ni.y = fmaf(iv.y, s1, fmaf(hv.y, s2, bvv));
                ni.z = fmaf(iv.z, s1, fmaf(hv.z, s2, bvv));
                ni.w = fmaf(iv.w, s1, fmaf(hv.w, s2, bvv));
                *(float4*)&itp[j * 4] = ni;
                if (layer == 0) {    // head update dead after last layer
                    float4 nh;
                    nh.x = fmaf(iv.x, s3, fmaf(hv.x, s4, bee));
                    nh.y = fmaf(iv.y, s3, fmaf(hv.y, s4, bee));
                    nh.z = fmaf(iv.z, s3, fmaf(hv.z, s4, bee));
                    nh.w = fmaf(iv.w, s3, fmaf(hv.w, s4, bee));
                    *(float4*)&hdp[j * 4] = nh;
                }
            }
        }
    }

    CP_WAIT(0);          // W1 landed
    __syncthreads();     // concat point: user cols + item cols + W1 all visible

    // ---- stage W2 (blocked K8=16) into the now-dead ping region; hides under GEMM1 ----
    #pragma unroll 8
    for (int i = 0; i < 32; i++) {
        int idx = t + i * 256;
        cpa4(uPing + 4u * bwoff(idx & 63, idx >> 6, 16), W2 + (idx >> 6) * 64 + (idx & 63));
    }
    CP_COMMIT();

    // ============ GEMM1: M=128, N=128, K=128; 8 warps = 2M x 4N, pipelined ============
    const int wm = wid & 1, wn4 = wid >> 1;
    {
        float acc[4][4][4];
        #pragma unroll
        for (int mt = 0; mt < 4; mt++)
            #pragma unroll
            for (int nt = 0; nt < 4; nt++)
                #pragma unroll
                for (int i = 0; i < 4; i++) acc[mt][nt][i] = 0.f;
        const int nb0 = wn4 * 4;
        uint32_t a[2][4][4], b[2][8];
        #pragma unroll
        for (int mt = 0; mt < 4; mt++)
            ldsm4(a[0][mt], uAct + 4u * ((wm * 64 + mt * 16) * SST) + aoffT);
        ldsm4(b[0],     uW1s + 4u * (((nb0 + 0) * 16) << 6) + boffT16);
        ldsm4(b[0] + 4, uW1s + 4u * (((nb0 + 2) * 16) << 6) + boffT16);
        #pragma unroll
        for (int k8 = 0; k8 < 16; k8++) {
            const int cur = k8 & 1, nxt = cur ^ 1;
            if (k8 < 15) {
                #pragma unroll
                for (int mt = 0; mt < 4; mt++)
                    ldsm4(a[nxt][mt], uAct + 4u * ((wm * 64 + mt * 16) * SST + (k8 + 1) * 8) + aoffT);
                ldsm4(b[nxt],     uW1s + 4u * (((nb0 + 0) * 16 + k8 + 1) << 6) + boffT16);
                ldsm4(b[nxt] + 4, uW1s + 4u * (((nb0 + 2) * 16 + k8 + 1) << 6) + boffT16);
            }
            #pragma unroll
            for (int mt = 0; mt < 4; mt++) {
                mma8(acc[mt][0], a[cur][mt], b[cur]);
                mma8(acc[mt][1], a[cur][mt], b[cur] + 2);
                mma8(acc[mt][2], a[cur][mt], b[cur] + 4);
                mma8(acc[mt][3], a[cur][mt], b[cur] + 6);
            }
        }
        __syncthreads();    // all GEMM1 reads done before h1 overwrites sAct
        const int r0b = wm * 64 + (l >> 2);
        const int cb  = wn4 * 32 + 2 * (l & 3);
        #pragma unroll
        for (int mt = 0; mt < 4; mt++)
            #pragma unroll
            for (int nt = 0; nt < 4; nt++) {
                int c = cb + nt * 8;
                float bb0 = sB1[c], bb1 = sB1[c + 1];
                int r0 = r0b + mt * 16;
                float2 v0, v1;
                v0.x = fmaxf(acc[mt][nt][0] + bb0, 0.f);
                v0.y = fmaxf(acc[mt][nt][1] + bb1, 0.f);
                v1.x = fmaxf(acc[mt][nt][2] + bb0, 0.f);
                v1.y = fmaxf(acc[mt][nt][3] + bb1, 0.f);
                *(float2*)&sAct[r0 * SST + c] = v0;
                *(float2*)&sAct[(r0 + 8) * SST + c] = v1;
            }
    }
    CP_WAIT(0);          // W2 landed
    __syncthreads();     // h1 + W2 visible

    // ============ GEMM2 (M=128, N=64; 2M x 4N of 16) + fused final 64->1, pipelined ============
    {
        float acc[4][2][4];
        #pragma unroll
        for (int mt = 0; mt < 4; mt++)
            #pragma unroll
            for (int nt = 0; nt < 2; nt++)
                #pragma unroll
                for (int i = 0; i < 4; i++) acc[mt][nt][i] = 0.f;
        const int nb0 = wn4 * 2;
        uint32_t a[2][4][4], b[2][4];
        #pragma unroll
        for (int mt = 0; mt < 4; mt++)
            ldsm4(a[0][mt], uAct + 4u * ((wm * 64 + mt * 16) * SST) + aoffT);
        ldsm4(b[0], uPing + 4u * ((nb0 * 16) << 6) + boffT16);
        #pragma unroll
        for (int k8 = 0; k8 < 16; k8++) {
            const int cur = k8 & 1, nxt = cur ^ 1;
            if (k8 < 15) {
                #pragma unroll
                for (int mt = 0; mt < 4; mt++)
                    ldsm4(a[nxt][mt], uAct + 4u * ((wm * 64 + mt * 16) * SST + (k8 + 1) * 8) + aoffT);
                ldsm4(b[nxt], uPing + 4u * ((nb0 * 16 + k8 + 1) << 6) + boffT16);
            }
            #pragma unroll
            for (int mt = 0; mt < 4; mt++) {
                mma8(acc[mt][0], a[cur][mt], b[cur]);
                mma8(acc[mt][1], a[cur][mt], b[cur] + 2);
            }
        }
        // fused: p[row] += relu(h2+b2)*w3, reduce over lane column-group, atomic into sOut
        const int cb = wn4 * 16 + 2 * (l & 3);
        float part[4][2];
        #pragma unroll
        for (int mt = 0; mt < 4; mt++) { part[mt][0] = 0.f; part[mt][1] = 0.f; }
        #pragma unroll
        for (int nt = 0; nt < 2; nt++) {
            int c = cb + nt * 8;
            float bb0 = sB2[c], bb1 = sB2[c + 1];
            float w30 = sW3[c], w31 = sW3[c + 1];
            #pragma unroll
            for (int mt = 0; mt < 4; mt++) {
                part[mt][0] = fmaf(fmaxf(acc[mt][nt][0] + bb0, 0.f), w30,
                              fmaf(fmaxf(acc[mt][nt][1] + bb1, 0.f), w31, part[mt][0]));
                part[mt][1] = fmaf(fmaxf(acc[mt][nt][2] + bb0, 0.f), w30,
                              fmaf(fmaxf(acc[mt][nt][3] + bb1, 0.f), w31, part[mt][1]));
            }
        }
        #pragma unroll
        for (int mt = 0; mt < 4; mt++)
            #pragma unroll
            for (int rh = 0; rh < 2; rh++) {
                part[mt][rh] += __shfl_xor_sync(0xffffffffu, part[mt][rh], 1);
                part[mt][rh] += __shfl_xor_sync(0xffffffffu, part[mt][rh], 2);
            }
        if ((l & 3) == 0) {
            const int r0b = wm * 64 + (l >> 2);
            #pragma unroll
            for (int mt = 0; mt < 4; mt++) {
                atomicAdd(&sOut[r0b + mt * 16],     part[mt][0]);
                atomicAdd(&sOut[r0b + mt * 16 + 8], part[mt][1]);
            }
        }
    }
    __syncthreads();

    // ============ output ============
    if (t < 128)
        out[base + t] = fmaxf(sOut[t] + __ldg(b3), 0.f);
}

extern "C" void kernel_launch(void* const* d_in, const int* in_sizes, int n_in,
                              void* d_out, int out_size)
{
    const int*   user_id    = (const int*)d_in[0];
    const int*   item_id    = (const int*)d_in[1];
    const float* rec_target = (const float*)d_in[2];
    const float* user_emb   = (const float*)d_in[3];
    const float* item_emb   = (const float*)d_in[4];
    const float* entity_emb = (const float*)d_in[5];
    const float* w_vv = (const float*)d_in[6];
    const float* w_ev = (const float*)d_in[7];
    const float* w_ve = (const float*)d_in[8];
    const float* w_ee = (const float*)d_in[9];
    const float* b_v  = (const float*)d_in[10];
    const float* b_e  = (const float*)d_in[11];
    const float* Wul  = (const float*)d_in[12];
    const float* bul  = (const float*)d_in[13];
    const float* W1   = (const float*)d_in[14];
    const float* b1   = (const float*)d_in[15];
    const float* W2   = (const float*)d_in[16];
    const float* b2   = (const float*)d_in[17];
    const float* W3   = (const float*)d_in[18];
    const float* b3   = (const float*)d_in[19];

    cudaFuncSetAttribute(multikr_mma_kernel,
                         cudaFuncAttributeMaxDynamicSharedMemorySize, SMEM_BYTES);

    const int n = in_sizes[0];      // 16384
    const int nblk = n / 128;       // 128 blocks, one wave
    multikr_mma_kernel<<<nblk, NT, SMEM_BYTES>>>(
        user_id, item_id, rec_target, user_emb, item_emb, entity_emb,
        w_vv, w_ev, w_ve, w_ee, b_v, b_e, Wul, bul,
        W1, b1, W2, b2, W3, b3,
        (float*)d_out, out_size);
}

// round 9
// speedup vs baseline: 1.3707x; 1.1379x over previous
#include <cuda_runtime.h>
#include <cstdint>

#define NT 256
#define SST 132            // sAct row stride; 528B: 16B-aligned, ldsm conflict-free
#define HST 68             // sHead / ping row stride; 272B ok
#define W1S 136            // W1 row stride (mod 32 == 8 -> B-LDS conflict-free)
#define WUS 72             // Wul / W2 row stride (mod 32 == 8)
#define BTOT 16384

// ---- dynamic smem layout (float offsets) ----
#define F_ACT   0                        // sAct[128][132] = 16896
#define F_W1    16896                    // W1 [128][136]  = 17408 (row-major, untransposed)
#define F_WUL   34304                    // Wul [64][72]   = 4608
#define F_HEAD  38912                    // sHead[128][68] = 8704
#define F_PING  47616                    // 9216: phase1 = user ping[128][68] (first 8704); later W2 [128][72]
#define F_WV    (F_PING + 8704)          // 256: w_vv|w_ev|w_ve|w_ee (dead before W2 staged)
#define F_BUL   (F_PING + 8960)          // 64  (dead before W2 staged)
#define F_B1    56832                    // 128
#define F_B2    (F_B1 + 128)             // 64
#define F_W3    (F_B2 + 64)              // 64
#define F_OUT   (F_W3 + 64)              // 128 (output accumulator)
#define SMEM_FLOATS (F_OUT + 128)        // 57216 floats = 228864 B
#define SMEM_BYTES  (SMEM_FLOATS * 4)

__device__ __forceinline__ uint32_t smem_u32(const void* p) {
    uint32_t a;
    asm("{ .reg .u64 t; cvta.to.shared.u64 t, %1; cvt.u32.u64 %0, t; }" : "=r"(a) : "l"(p));
    return a;
}
__device__ __forceinline__ void ldsm4(uint32_t* r, uint32_t addr) {
    asm volatile("ldmatrix.sync.aligned.m8n8.x4.shared.b16 {%0,%1,%2,%3}, [%4];"
                 : "=r"(r[0]), "=r"(r[1]), "=r"(r[2]), "=r"(r[3]) : "r"(addr));
}
__device__ __forceinline__ void mma8(float* c, const uint32_t* a, const uint32_t* b) {
    asm("mma.sync.aligned.m16n8k8.row.col.f32.tf32.tf32.f32 "
        "{%0,%1,%2,%3},{%4,%5,%6,%7},{%8,%9},{%0,%1,%2,%3};"
        : "+f"(c[0]), "+f"(c[1]), "+f"(c[2]), "+f"(c[3])
        : "r"(a[0]), "r"(a[1]), "r"(a[2]), "r"(a[3]), "r"(b[0]), "r"(b[1]));
}
__device__ __forceinline__ void cpa16(uint32_t dst, const void* src) {
    asm volatile("cp.async.cg.shared.global [%0], [%1], 16;" :: "r"(dst), "l"(src));
}
__device__ __forceinline__ void cpa4(uint32_t dst, const void* src) {
    asm volatile("cp.async.ca.shared.global [%0], [%1], 4;" :: "r"(dst), "l"(src));
}
#define CP_COMMIT() asm volatile("cp.async.commit_group;" ::: "memory")
#define CP_WAIT(n)  asm volatile("cp.async.wait_group %0;" :: "n"(n) : "memory")
#define BAR_U() asm volatile("bar.sync 1, 128;" ::: "memory")
#define BAR_C() asm volatile("bar.sync 2, 128;" ::: "memory")

__global__ __launch_bounds__(NT, 1)
void multikr_mma_kernel(const int* __restrict__ user_id,
                        const int* __restrict__ item_id,
                        const float* __restrict__ rec_target,
                        const float* __restrict__ user_emb,
                        const float* __restrict__ item_emb,
                        const float* __restrict__ entity_emb,
                        const float* __restrict__ w_vv,
                        const float* __restrict__ w_ev,
                        const float* __restrict__ w_ve,
                        const float* __restrict__ w_ee,
                        const float* __restrict__ b_v,
                        const float* __restrict__ b_e,
                        const float* __restrict__ Wul,
                        const float* __restrict__ bul,
                        const float* __restrict__ W1,
                        const float* __restrict__ b1,
                        const float* __restrict__ W2,
                        const float* __restrict__ b2,
                        const float* __restrict__ W3,
                        const float* __restrict__ b3,
                        float* __restrict__ out,
                        int out_size)
{
    extern __shared__ float sm[];
    float* sAct  = sm + F_ACT;
    float* sW1   = sm + F_W1;
    float* sWul  = sm + F_WUL;
    float* sHead = sm + F_HEAD;
    float* sPing = sm + F_PING;     // user ping in phase 1; W2 [128][72] afterwards
    float* sW2   = sm + F_PING;
    float* sWV   = sm + F_WV;
    float* sBUL  = sm + F_BUL;
    float* sB1   = sm + F_B1;
    float* sB2   = sm + F_B2;
    float* sW3   = sm + F_W3;
    float* sOut  = sm + F_OUT;

    const int t    = threadIdx.x;
    const int l    = t & 31;
    const int wid  = t >> 5;
    const int mtx  = l >> 3, p = l & 7;
    const int base = blockIdx.x * 128;

    const uint32_t uAct  = smem_u32(sAct);
    const uint32_t uW1s  = smem_u32(sW1);
    const uint32_t uWuls = smem_u32(sWul);
    const uint32_t uPing = smem_u32(sPing);
    const uint32_t uHead = smem_u32(sHead);
    const uint32_t uWVs  = smem_u32(sWV);
    const uint32_t uBULs = smem_u32(sBUL);
    const uint32_t uB1s  = smem_u32(sB1);
    const uint32_t uB2s  = smem_u32(sB2);
    const uint32_t uW3s  = smem_u32(sW3);

    // A-operand ldsm per-thread offsets (bytes)
    const uint32_t aoffT = 4u * (((mtx & 1) * 8 + p) * SST + (mtx >> 1) * 4);
    const uint32_t aoffP = 4u * (((mtx & 1) * 8 + p) * HST + (mtx >> 1) * 4);
    // B-operand direct-LDS per-thread base (floats): B[k=(l&3)][n=(l>>2)]
    const int bl = l & 3, bn = l >> 2;

    // ============ async front-end (16B copies, untransposed weights) ============
    if (t < 128) {
        // G0 (user warps): Wul rows + user gather + bul
        #pragma unroll
        for (int i = 0; i < 8; i++) {           // Wul: 64 rows x 16 segs
            int idx = t + i * 128;
            int r = idx >> 4, sg = idx & 15;
            cpa16(uWuls + 4u * (r * WUS + sg * 4), Wul + r * 64 + sg * 4);
        }
        #pragma unroll
        for (int i = 0; i < 16; i++) {          // user embedding gather
            int cid = t + i * 128;
            int s = cid >> 4, j = cid & 15;
            int uid = __ldg(user_id + base + s);
            cpa16(uAct + 4u * (s * SST + j * 4), user_emb + (size_t)uid * 64 + j * 4);
        }
        if (t < 64) cpa4(uBULs + 4u * t, bul + t);
        CP_COMMIT();
        CP_COMMIT();    // empty G1
    } else {
        const int ct = t - 128;
        // G0 (cross warps): WV + b1/b2/w3
        {
            const float* w1p = (ct < 64) ? (w_vv + ct) : (w_ev + ct - 64);
            const float* w2p = (ct < 64) ? (w_ve + ct) : (w_ee + ct - 64);
            cpa4(uWVs + 4u * ct, w1p);
            cpa4(uWVs + 4u * (128 + ct), w2p);
            cpa4(uB1s + 4u * ct, b1 + ct);
            if (ct < 64) { cpa4(uB2s + 4u * ct, b2 + ct); cpa4(uW3s + 4u * ct, W3 + ct); }
        }
        CP_COMMIT();
        // G1: item + head gathers
        #pragma unroll
        for (int i = 0; i < 16; i++) {
            int cid = ct + i * 128;
            int s = cid >> 4, j = cid & 15;
            int iid = __ldg(item_id + base + s);
            cpa16(uAct + 4u * (s * SST + 64 + j * 4), item_emb + (size_t)iid * 64 + j * 4);
            cpa16(uHead + 4u * (s * HST + j * 4), entity_emb + (size_t)iid * 64 + j * 4);
        }
        CP_COMMIT();
    }
    // G2: W1 rows (all threads): 128 rows x 32 segs
    #pragma unroll
    for (int i = 0; i < 16; i++) {
        int idx = t + i * 256;
        int r = idx >> 5, sg = idx & 31;
        cpa16(uW1s + 4u * (r * W1S + sg * 4), W1 + r * 128 + sg * 4);
    }
    CP_COMMIT();

    // rec_target passthrough (independent; overlaps cp.async)
    if (t >= 128 && out_size >= 2 * BTOT)
        out[BTOT + base + (t - 128)] = __ldg(rec_target + base + (t - 128));

    // ============ phase 1: user MLP chain (warps 0-3) || cross chain (warps 4-7) ============
    if (t < 128) {
        const int wm = wid & 1, wn = wid >> 1;    // M half (64 rows), N half (32 cols)
        const int nb = wn * 32;
        const float* bWul = sWul + bl * WUS + bn + nb;
        CP_WAIT(2);                               // G0 (Wul+user+bul) landed
        BAR_U();
        sOut[t] = 0.f;

        // ---- layer 1: read sAct cols 0-63, write ping ----
        // ---- layer 2: read ping, write sAct cols 0-63 ----
        #pragma unroll 1
        for (int layer = 0; layer < 2; layer++) {
            float acc[4][4][4];
            #pragma unroll
            for (int mt = 0; mt < 4; mt++)
                #pragma unroll
                for (int nt = 0; nt < 4; nt++)
                    #pragma unroll
                    for (int i = 0; i < 4; i++) acc[mt][nt][i] = 0.f;
            #pragma unroll
            for (int k8 = 0; k8 < 8; k8++) {
                uint32_t a[4][4], b[4][2];
                #pragma unroll
                for (int mt = 0; mt < 4; mt++) {
                    uint32_t ad = layer ? (uPing + 4u * ((wm * 64 + mt * 16) * HST + k8 * 8) + aoffP)
                                        : (uAct  + 4u * ((wm * 64 + mt * 16) * SST + k8 * 8) + aoffT);
                    ldsm4(a[mt], ad);
                }
                const float* bp = bWul + k8 * 8 * WUS;
                #pragma unroll
                for (int nt = 0; nt < 4; nt++) {
                    b[nt][0] = __float_as_uint(bp[nt * 8]);
                    b[nt][1] = __float_as_uint(bp[nt * 8 + 4 * WUS]);
                }
                #pragma unroll
                for (int mt = 0; mt < 4; mt++)
                    #pragma unroll
                    for (int nt = 0; nt < 4; nt++)
                        mma8(acc[mt][nt], a[mt], b[nt]);
            }
            if (layer == 0) BAR_U();   // reads of sAct done before... (write target is ping, barrier for ping WAR-free; this orders nothing harmful)
            const int r0b = wm * 64 + (l >> 2);
            const int cb  = nb + 2 * (l & 3);
            #pragma unroll
            for (int mt = 0; mt < 4; mt++)
                #pragma unroll
                for (int nt = 0; nt < 4; nt++) {
                    int c = cb + nt * 8;
                    float bb0 = sBUL[c], bb1 = sBUL[c + 1];
                    int r0 = r0b + mt * 16;
                    float2 v0, v1;
                    v0.x = fmaxf(acc[mt][nt][0] + bb0, 0.f);
                    v0.y = fmaxf(acc[mt][nt][1] + bb1, 0.f);
                    v1.x = fmaxf(acc[mt][nt][2] + bb0, 0.f);
                    v1.y = fmaxf(acc[mt][nt][3] + bb1, 0.f);
                    if (layer == 0) {
                        *(float2*)&sPing[r0 * HST + c] = v0;
                        *(float2*)&sPing[(r0 + 8) * HST + c] = v1;
                    } else {
                        *(float2*)&sAct[r0 * SST + c] = v0;
                        *(float2*)&sAct[(r0 + 8) * SST + c] = v1;
                    }
                }
            BAR_U();   // layer output visible to all user warps
        }
    } else {
        const int s = t - 128;                    // 1 thread per sample
        const float bvv = __ldg(b_v), bee = __ldg(b_e);
        CP_WAIT(1);                               // G0 + G1 landed
        BAR_C();
        float* itp = &sAct[s * SST + 64];
        float* hdp = &sHead[s * HST];
        #pragma unroll 1
        for (int layer = 0; layer < 2; layer++) {
            float s1 = 0.f, s2 = 0.f, s3 = 0.f, s4 = 0.f;
            #pragma unroll
            for (int j = 0; j < 16; j++) {
                float4 iv = *(const float4*)&itp[j * 4];
                float4 hv = *(const float4*)&hdp[j * 4];
                float4 wvv = *(const float4*)&sWV[j * 4];
                float4 wev = *(const float4*)&sWV[64 + j * 4];
                s1 = fmaf(hv.x, wvv.x, fmaf(hv.y, wvv.y, fmaf(hv.z, wvv.z, fmaf(hv.w, wvv.w, s1))));
                s2 = fmaf(iv.x, wev.x, fmaf(iv.y, wev.y, fmaf(iv.z, wev.z, fmaf(iv.w, wev.w, s2))));
                if (layer == 0) {
                    float4 wve = *(const float4*)&sWV[128 + j * 4];
                    float4 wee = *(const float4*)&sWV[192 + j * 4];
                    s3 = fmaf(hv.x, wve.x, fmaf(hv.y, wve.y, fmaf(hv.z, wve.z, fmaf(hv.w, wve.w, s3))));
                    s4 = fmaf(iv.x, wee.x, fmaf(iv.y, wee.y, fmaf(iv.z, wee.z, fmaf(iv.w, wee.w, s4))));
                }
            }
            #pragma unroll
            for (int j = 0; j < 16; j++) {
                float4 iv = *(const float4*)&itp[j * 4];
                float4 hv = *(const float4*)&hdp[j * 4];
                float4 ni;
                ni.x = fmaf(iv.x, s1, fmaf(hv.x, s2, bvv));
                ni.y = fmaf(iv.y, s1, fmaf(hv.y, s2, bvv));
                ni.z = fmaf(iv.z, s1, fmaf(hv.z, s2, bvv));
                ni.w = fmaf(iv.w, s1, fmaf(hv.w, s2, bvv));
                *(float4*)&itp[j * 4] = ni;
                if (layer == 0) {     // head update dead after last layer
                    float4 nh;
                    nh.x = fmaf(iv.x, s3, fmaf(hv.x, s4, bee));
                    nh.y = fmaf(iv.y, s3, fmaf(hv.y, s4, bee));
                    nh.z = fmaf(iv.z, s3, fmaf(hv.z, s4, bee));
                    nh.w = fmaf(iv.w, s3, fmaf(hv.w, s4, bee));
                    *(float4*)&hdp[j * 4] = nh;
                }
            }
        }
    }

    CP_WAIT(0);          // W1 landed
    __syncthreads();     // concat point: user cols + item cols + W1 visible; WV/BUL/ping dead

    // ---- stage W2 rows into the dead ping region (hides under GEMM1) ----
    #pragma unroll
    for (int i = 0; i < 8; i++) {               // 128 rows x 16 segs
        int idx = t + i * 256;
        int r = idx >> 4, sg = idx & 15;
        cpa16(uPing + 4u * (r * WUS + sg * 4), W2 + r * 64 + sg * 4);
    }
    CP_COMMIT();

    // ============ GEMM1: M=128, N=128, K=128; 8 warps = 2M x 4N ============
    const int wm = wid & 1, wn4 = wid >> 1;
    {
        float acc[4][4][4];
        #pragma unroll
        for (int mt = 0; mt < 4; mt++)
            #pragma unroll
            for (int nt = 0; nt < 4; nt++)
                #pragma unroll
                for (int i = 0; i < 4; i++) acc[mt][nt][i] = 0.f;
        const int nb = wn4 * 32;
        const float* bW1 = sW1 + bl * W1S + bn + nb;
        #pragma unroll
        for (int k8 = 0; k8 < 16; k8++) {
            uint32_t a[4][4], b[4][2];
            #pragma unroll
            for (int mt = 0; mt < 4; mt++)
                ldsm4(a[mt], uAct + 4u * ((wm * 64 + mt * 16) * SST + k8 * 8) + aoffT);
            const float* bp = bW1 + k8 * 8 * W1S;
            #pragma unroll
            for (int nt = 0; nt < 4; nt++) {
                b[nt][0] = __float_as_uint(bp[nt * 8]);
                b[nt][1] = __float_as_uint(bp[nt * 8 + 4 * W1S]);
            }
            #pragma unroll
            for (int mt = 0; mt < 4; mt++)
                #pragma unroll
                for (int nt = 0; nt < 4; nt++)
                    mma8(acc[mt][nt], a[mt], b[nt]);
        }
        __syncthreads();    // all GEMM1 reads done before h1 overwrites sAct
        const int r0b = wm * 64 + (l >> 2);
        const int cb  = nb + 2 * (l & 3);
        #pragma unroll
        for (int mt = 0; mt < 4; mt++)
            #pragma unroll
            for (int nt = 0; nt < 4; nt++) {
                int c = cb + nt * 8;
                float bb0 = sB1[c], bb1 = sB1[c + 1];
                int r0 = r0b + mt * 16;
                float2 v0, v1;
                v0.x = fmaxf(acc[mt][nt][0] + bb0, 0.f);
                v0.y = fmaxf(acc[mt][nt][1] + bb1, 0.f);
                v1.x = fmaxf(acc[mt][nt][2] + bb0, 0.f);
                v1.y = fmaxf(acc[mt][nt][3] + bb1, 0.f);
                *(float2*)&sAct[r0 * SST + c] = v0;
                *(float2*)&sAct[(r0 + 8) * SST + c] = v1;
            }
    }
    CP_WAIT(0);          // W2 landed
    __syncthreads();     // h1 + W2 visible

    // ============ GEMM2: M=128, N=64; 8 warps = 4M x 2N (32x32 tiles) + fused 64->1 ============
    {
        const int wm3 = wid & 3, wn3 = wid >> 2;
        float acc[2][4][4];
        #pragma unroll
        for (int mt = 0; mt < 2; mt++)
            #pragma unroll
            for (int nt = 0; nt < 4; nt++)
                #pragma unroll
                for (int i = 0; i < 4; i++) acc[mt][nt][i] = 0.f;
        const int nb2 = wn3 * 32;
        const float* bW2 = sW2 + bl * WUS + bn + nb2;
        #pragma unroll
        for (int k8 = 0; k8 < 16; k8++) {
            uint32_t a[2][4], b[4][2];
            #pragma unroll
            for (int mt = 0; mt < 2; mt++)
                ldsm4(a[mt], uAct + 4u * ((wm3 * 32 + mt * 16) * SST + k8 * 8) + aoffT);
            const float* bp = bW2 + k8 * 8 * WUS;
            #pragma unroll
            for (int nt = 0; nt < 4; nt++) {
                b[nt][0] = __float_as_uint(bp[nt * 8]);
                b[nt][1] = __float_as_uint(bp[nt * 8 + 4 * WUS]);
            }
            #pragma unroll
            for (int mt = 0; mt < 2; mt++)
                #pragma unroll
                for (int nt = 0; nt < 4; nt++)
                    mma8(acc[mt][nt], a[mt], b[nt]);
        }
        // fused: p[row] += relu(h2+b2)*w3, reduce over 4-lane col groups, atomic into sOut
        const int cb = nb2 + 2 * (l & 3);
        float part[2][2];
        part[0][0] = part[0][1] = part[1][0] = part[1][1] = 0.f;
        #pragma unroll
        for (int nt = 0; nt < 4; nt++) {
            int c = cb + nt * 8;
            float bb0 = sB2[c], bb1 = sB2[c + 1];
            float w30 = sW3[c], w31 = sW3[c + 1];
            #pragma unroll
            for (int mt = 0; mt < 2; mt++) {
                part[mt][0] = fmaf(fmaxf(acc[mt][nt][0] + bb0, 0.f), w30,
                              fmaf(fmaxf(acc[mt][nt][1] + bb1, 0.f), w31, part[mt][0]));
                part[mt][1] = fmaf(fmaxf(acc[mt][nt][2] + bb0, 0.f), w30,
                              fmaf(fmaxf(acc[mt][nt][3] + bb1, 0.f), w31, part[mt][1]));
            }
        }
        #pragma unroll
        for (int mt = 0; mt < 2; mt++)
            #pragma unroll
            for (int rh = 0; rh < 2; rh++) {
                part[mt][rh] += __shfl_xor_sync(0xffffffffu, part[mt][rh], 1);
                part[mt][rh] += __shfl_xor_sync(0xffffffffu, part[mt][rh], 2);
            }
        if ((l & 3) == 0) {
            const int r0b = wm3 * 32 + (l >> 2);
            #pragma unroll
            for (int mt = 0; mt < 2; mt++) {
                atomicAdd(&sOut[r0b + mt * 16],     part[mt][0]);
                atomicAdd(&sOut[r0b + mt * 16 + 8], part[mt][1]);
            }
        }
    }
    __syncthreads();

    // ============ output ============
    if (t < 128)
        out[base + t] = fmaxf(sOut[t] + __ldg(b3), 0.f);
}

extern "C" void kernel_launch(void* const* d_in, const int* in_sizes, int n_in,
                              void* d_out, int out_size)
{
    const int*   user_id    = (const int*)d_in[0];
    const int*   item_id    = (const int*)d_in[1];
    const float* rec_target = (const float*)d_in[2];
    const float* user_emb   = (const float*)d_in[3];
    const float* item_emb   = (const float*)d_in[4];
    const float* entity_emb = (const float*)d_in[5];
    const float* w_vv = (const float*)d_in[6];
    const float* w_ev = (const float*)d_in[7];
    const float* w_ve = (const float*)d_in[8];
    const float* w_ee = (const float*)d_in[9];
    const float* b_v  = (const float*)d_in[10];
    const float* b_e  = (const float*)d_in[11];
    const float* Wul  = (const float*)d_in[12];
    const float* bul  = (const float*)d_in[13];
    const float* W1   = (const float*)d_in[14];
    const float* b1   = (const float*)d_in[15];
    const float* W2   = (const float*)d_in[16];
    const float* b2   = (const float*)d_in[17];
    const float* W3   = (const float*)d_in[18];
    const float* b3   = (const float*)d_in[19];

    cudaFuncSetAttribute(multikr_mma_kernel,
                         cudaFuncAttributeMaxDynamicSharedMemorySize, SMEM_BYTES);

    const int n = in_sizes[0];      // 16384
    const int nblk = n / 128;       // 128 blocks, one wave
    multikr_mma_kernel<<<nblk, NT, SMEM_BYTES>>>(
        user_id, item_id, rec_target, user_emb, item_emb, entity_emb,
        w_vv, w_ev, w_ve, w_ee, b_v, b_e, Wul, bul,
        W1, b1, W2, b2, W3, b3,
        (float*)d_out, out_size);
}

// round 10
// speedup vs baseline: 1.3766x; 1.0043x over previous
#include <cuda_runtime.h>
#include <cstdint>

#define NT 256
#define SST 132            // sAct row stride; 528B: 16B-aligned, ldsm conflict-free
#define HST 68             // sHead / ping row stride; 272B ok
#define W1S 136            // W1 row stride (mod 32 == 8 -> B-LDS conflict-free)
#define WUS 72             // Wul / W2 row stride (mod 32 == 8)
#define BTOT 16384

// ---- dynamic smem layout (float offsets) ----
#define F_ACT   0                        // sAct[128][132] = 16896
#define F_W1    16896                    // W1 [128][136]  = 17408 (row-major, untransposed)
#define F_WUL   34304                    // Wul [64][72]   = 4608
#define F_HEAD  38912                    // sHead[128][68] = 8704
#define F_PING  47616                    // phase1 = user ping[128][68]; later W2 [128][72]
#define F_WV    (F_PING + 8704)          // 256 (dead before W2 staged)
#define F_BUL   (F_PING + 8960)          // 64  (dead before W2 staged)
#define F_B1    56832                    // 128
#define F_B2    (F_B1 + 128)             // 64
#define F_W3    (F_B2 + 64)              // 64
#define F_OUT   (F_W3 + 64)              // 128 (output accumulator)
#define SMEM_FLOATS (F_OUT + 128)        // 57216 floats = 228864 B
#define SMEM_BYTES  (SMEM_FLOATS * 4)

__device__ __forceinline__ uint32_t smem_u32(const void* p) {
    uint32_t a;
    asm("{ .reg .u64 t; cvta.to.shared.u64 t, %1; cvt.u32.u64 %0, t; }" : "=r"(a) : "l"(p));
    return a;
}
__device__ __forceinline__ void ldsm4(uint32_t* r, uint32_t addr) {
    asm volatile("ldmatrix.sync.aligned.m8n8.x4.shared.b16 {%0,%1,%2,%3}, [%4];"
                 : "=r"(r[0]), "=r"(r[1]), "=r"(r[2]), "=r"(r[3]) : "r"(addr));
}
__device__ __forceinline__ void mma8(float* c, const uint32_t* a, const uint32_t* b) {
    asm("mma.sync.aligned.m16n8k8.row.col.f32.tf32.tf32.f32 "
        "{%0,%1,%2,%3},{%4,%5,%6,%7},{%8,%9},{%0,%1,%2,%3};"
        : "+f"(c[0]), "+f"(c[1]), "+f"(c[2]), "+f"(c[3])
        : "r"(a[0]), "r"(a[1]), "r"(a[2]), "r"(a[3]), "r"(b[0]), "r"(b[1]));
}
__device__ __forceinline__ void cpa16(uint32_t dst, const void* src) {
    asm volatile("cp.async.cg.shared.global [%0], [%1], 16;" :: "r"(dst), "l"(src));
}
__device__ __forceinline__ void cpa4(uint32_t dst, const void* src) {
    asm volatile("cp.async.ca.shared.global [%0], [%1], 4;" :: "r"(dst), "l"(src));
}
#define CP_COMMIT() asm volatile("cp.async.commit_group;" ::: "memory")
#define CP_WAIT(n)  asm volatile("cp.async.wait_group %0;" :: "n"(n) : "memory")
#define BAR_U() asm volatile("bar.sync 1, 128;" ::: "memory")
#define BAR_C() asm volatile("bar.sync 2, 128;" ::: "memory")
#define BAR_G(g) asm volatile("bar.sync %0, 128;" :: "r"((g) + 1) : "memory")

__global__ __launch_bounds__(NT, 1)
void multikr_mma_kernel(const int* __restrict__ user_id,
                        const int* __restrict__ item_id,
                        const float* __restrict__ rec_target,
                        const float* __restrict__ user_emb,
                        const float* __restrict__ item_emb,
                        const float* __restrict__ entity_emb,
                        const float* __restrict__ w_vv,
                        const float* __restrict__ w_ev,
                        const float* __restrict__ w_ve,
                        const float* __restrict__ w_ee,
                        const float* __restrict__ b_v,
                        const float* __restrict__ b_e,
                        const float* __restrict__ Wul,
                        const float* __restrict__ bul,
                        const float* __restrict__ W1,
                        const float* __restrict__ b1,
                        const float* __restrict__ W2,
                        const float* __restrict__ b2,
                        const float* __restrict__ W3,
                        const float* __restrict__ b3,
                        float* __restrict__ out,
                        int out_size)
{
    extern __shared__ float sm[];
    float* sAct  = sm + F_ACT;
    float* sW1   = sm + F_W1;
    float* sWul  = sm + F_WUL;
    float* sHead = sm + F_HEAD;
    float* sPing = sm + F_PING;     // user ping in phase 1; W2 [128][72] afterwards
    float* sW2   = sm + F_PING;
    float* sWV   = sm + F_WV;
    float* sBUL  = sm + F_BUL;
    float* sB1   = sm + F_B1;
    float* sB2   = sm + F_B2;
    float* sW3   = sm + F_W3;
    float* sOut  = sm + F_OUT;

    const int t    = threadIdx.x;
    const int l    = t & 31;
    const int wid  = t >> 5;
    const int mtx  = l >> 3, p = l & 7;
    const int base = blockIdx.x * 128;

    const uint32_t uAct  = smem_u32(sAct);
    const uint32_t uW1s  = smem_u32(sW1);
    const uint32_t uWuls = smem_u32(sWul);
    const uint32_t uPing = smem_u32(sPing);
    const uint32_t uHead = smem_u32(sHead);
    const uint32_t uWVs  = smem_u32(sWV);
    const uint32_t uBULs = smem_u32(sBUL);
    const uint32_t uB1s  = smem_u32(sB1);
    const uint32_t uB2s  = smem_u32(sB2);
    const uint32_t uW3s  = smem_u32(sW3);

    // A-operand ldsm per-thread offsets (bytes)
    const uint32_t aoffT = 4u * (((mtx & 1) * 8 + p) * SST + (mtx >> 1) * 4);
    const uint32_t aoffP = 4u * (((mtx & 1) * 8 + p) * HST + (mtx >> 1) * 4);
    // B-operand direct-LDS per-thread base (floats): B[k=(l&3)][n=(l>>2)]
    const int bl = l & 3, bn = l >> 2;

    // ============ async front-end (16B copies, untransposed weights) ============
    if (t < 128) {
        // G0 (user warps): Wul rows + user gather + bul
        #pragma unroll
        for (int i = 0; i < 8; i++) {           // Wul: 64 rows x 16 segs
            int idx = t + i * 128;
            int r = idx >> 4, sg = idx & 15;
            cpa16(uWuls + 4u * (r * WUS + sg * 4), Wul + r * 64 + sg * 4);
        }
        #pragma unroll
        for (int i = 0; i < 16; i++) {          // user embedding gather
            int cid = t + i * 128;
            int s = cid >> 4, j = cid & 15;
            int uid = __ldg(user_id + base + s);
            cpa16(uAct + 4u * (s * SST + j * 4), user_emb + (size_t)uid * 64 + j * 4);
        }
        if (t < 64) cpa4(uBULs + 4u * t, bul + t);
        CP_COMMIT();
        CP_COMMIT();    // empty G1
    } else {
        const int ct = t - 128;
        // G0 (cross warps): WV + b1/b2/w3
        {
            const float* w1p = (ct < 64) ? (w_vv + ct) : (w_ev + ct - 64);
            const float* w2p = (ct < 64) ? (w_ve + ct) : (w_ee + ct - 64);
            cpa4(uWVs + 4u * ct, w1p);
            cpa4(uWVs + 4u * (128 + ct), w2p);
            cpa4(uB1s + 4u * ct, b1 + ct);
            if (ct < 64) { cpa4(uB2s + 4u * ct, b2 + ct); cpa4(uW3s + 4u * ct, W3 + ct); }
        }
        CP_COMMIT();
        // G1: item + head gathers
        #pragma unroll
        for (int i = 0; i < 16; i++) {
            int cid = ct + i * 128;
            int s = cid >> 4, j = cid & 15;
            int iid = __ldg(item_id + base + s);
            cpa16(uAct + 4u * (s * SST + 64 + j * 4), item_emb + (size_t)iid * 64 + j * 4);
            cpa16(uHead + 4u * (s * HST + j * 4), entity_emb + (size_t)iid * 64 + j * 4);
        }
        CP_COMMIT();
    }
    // G2: W1 rows (all threads): 128 rows x 32 segs
    #pragma unroll
    for (int i = 0; i < 16; i++) {
        int idx = t + i * 256;
        int r = idx >> 5, sg = idx & 31;
        cpa16(uW1s + 4u * (r * W1S + sg * 4), W1 + r * 128 + sg * 4);
    }
    CP_COMMIT();

    // rec_target passthrough (independent; overlaps cp.async)
    if (t >= 128 && out_size >= 2 * BTOT)
        out[BTOT + base + (t - 128)] = __ldg(rec_target + base + (t - 128));

    // ============ phase 1: user MLP chain (warps 0-3) || cross chain (warps 4-7) ============
    if (t < 128) {
        const int wm = wid & 1, wn = wid >> 1;    // M half (64 rows), N half (32 cols)
        const int nb = wn * 32;
        const float* bWul = sWul + bl * WUS + bn + nb;
        CP_WAIT(2);                               // G0 (Wul+user+bul) landed
        BAR_U();
        sOut[t] = 0.f;

        // ---- layer 1: read sAct cols 0-63, write ping; layer 2: read ping, write sAct ----
        #pragma unroll 1
        for (int layer = 0; layer < 2; layer++) {
            float acc[4][4][4];
            #pragma unroll
            for (int mt = 0; mt < 4; mt++)
                #pragma unroll
                for (int nt = 0; nt < 4; nt++)
                    #pragma unroll
                    for (int i = 0; i < 4; i++) acc[mt][nt][i] = 0.f;
            #pragma unroll
            for (int k8 = 0; k8 < 8; k8++) {
                uint32_t a[4][4], b[4][2];
                #pragma unroll
                for (int mt = 0; mt < 4; mt++) {
                    uint32_t ad = layer ? (uPing + 4u * ((wm * 64 + mt * 16) * HST + k8 * 8) + aoffP)
                                        : (uAct  + 4u * ((wm * 64 + mt * 16) * SST + k8 * 8) + aoffT);
                    ldsm4(a[mt], ad);
                }
                const float* bp = bWul + k8 * 8 * WUS;
                #pragma unroll
                for (int nt = 0; nt < 4; nt++) {
                    b[nt][0] = __float_as_uint(bp[nt * 8]);
                    b[nt][1] = __float_as_uint(bp[nt * 8 + 4 * WUS]);
                }
                #pragma unroll
                for (int mt = 0; mt < 4; mt++)
                    #pragma unroll
                    for (int nt = 0; nt < 4; nt++)
                        mma8(acc[mt][nt], a[mt], b[nt]);
            }
            const int r0b = wm * 64 + (l >> 2);
            const int cb  = nb + 2 * (l & 3);
            #pragma unroll
            for (int mt = 0; mt < 4; mt++)
                #pragma unroll
                for (int nt = 0; nt < 4; nt++) {
                    int c = cb + nt * 8;
                    float bb0 = sBUL[c], bb1 = sBUL[c + 1];
                    int r0 = r0b + mt * 16;
                    float2 v0, v1;
                    v0.x = fmaxf(acc[mt][nt][0] + bb0, 0.f);
                    v0.y = fmaxf(acc[mt][nt][1] + bb1, 0.f);
                    v1.x = fmaxf(acc[mt][nt][2] + bb0, 0.f);
                    v1.y = fmaxf(acc[mt][nt][3] + bb1, 0.f);
                    if (layer == 0) {
                        *(float2*)&sPing[r0 * HST + c] = v0;
                        *(float2*)&sPing[(r0 + 8) * HST + c] = v1;
                    } else {
                        *(float2*)&sAct[r0 * SST + c] = v0;
                        *(float2*)&sAct[(r0 + 8) * SST + c] = v1;
                    }
                }
            if (layer == 0) BAR_U();   // ping visible before layer-2 reads (only needed barrier)
        }
    } else {
        const int s = t - 128;                    // 1 thread per sample
        const float bvv = __ldg(b_v), bee = __ldg(b_e);
        CP_WAIT(1);                               // G0 + G1 landed
        BAR_C();
        float* itp = &sAct[s * SST + 64];
        float* hdp = &sHead[s * HST];
        #pragma unroll 1
        for (int layer = 0; layer < 2; layer++) {
            float s1 = 0.f, s2 = 0.f, s3 = 0.f, s4 = 0.f;
            #pragma unroll
            for (int j = 0; j < 16; j++) {
                float4 iv = *(const float4*)&itp[j * 4];
                float4 hv = *(const float4*)&hdp[j * 4];
                float4 wvv = *(const float4*)&sWV[j * 4];
                float4 wev = *(const float4*)&sWV[64 + j * 4];
                s1 = fmaf(hv.x, wvv.x, fmaf(hv.y, wvv.y, fmaf(hv.z, wvv.z, fmaf(hv.w, wvv.w, s1))));
                s2 = fmaf(iv.x, wev.x, fmaf(iv.y, wev.y, fmaf(iv.z, wev.z, fmaf(iv.w, wev.w, s2))));
                if (layer == 0) {
                    float4 wve = *(const float4*)&sWV[128 + j * 4];
                    float4 wee = *(const float4*)&sWV[192 + j * 4];
                    s3 = fmaf(hv.x, wve.x, fmaf(hv.y, wve.y, fmaf(hv.z, wve.z, fmaf(hv.w, wve.w, s3))));
                    s4 = fmaf(iv.x, wee.x, fmaf(iv.y, wee.y, fmaf(iv.z, wee.z, fmaf(iv.w, wee.w, s4))));
                }
            }
            #pragma unroll
            for (int j = 0; j < 16; j++) {
                float4 iv = *(const float4*)&itp[j * 4];
                float4 hv = *(const float4*)&hdp[j * 4];
                float4 ni;
                ni.x = fmaf(iv.x, s1, fmaf(hv.x, s2, bvv));
                ni.y = fmaf(iv.y, s1, fmaf(hv.y, s2, bvv));
                ni.z = fmaf(iv.z, s1, fmaf(hv.z, s2, bvv));
                ni.w = fmaf(iv.w, s1, fmaf(hv.w, s2, bvv));
                *(float4*)&itp[j * 4] = ni;
                if (layer == 0) {     // head update dead after last layer
                    float4 nh;
                    nh.x = fmaf(iv.x, s3, fmaf(hv.x, s4, bee));
                    nh.y = fmaf(iv.y, s3, fmaf(hv.y, s4, bee));
                    nh.z = fmaf(iv.z, s3, fmaf(hv.z, s4, bee));
                    nh.w = fmaf(iv.w, s3, fmaf(hv.w, s4, bee));
                    *(float4*)&hdp[j * 4] = nh;
                }
            }
        }
    }

    CP_WAIT(0);          // W1 landed
    __syncthreads();     // concat point: user cols + item cols + W1 visible; WV/BUL/ping dead

    // ---- stage W2 rows into the dead ping region (hides under GEMM1) ----
    #pragma unroll
    for (int i = 0; i < 8; i++) {               // 128 rows x 16 segs
        int idx = t + i * 256;
        int r = idx >> 4, sg = idx & 15;
        cpa16(uPing + 4u * (r * WUS + sg * 4), W2 + r * 64 + sg * 4);
    }
    CP_COMMIT();

    // ============ GEMM1: row-grouped. group g2 = warps [g2*4, g2*4+3] owns rows g2*64..+63 ============
    const int g2 = wid >> 2;       // row group
    const int w4 = wid & 3;        // N quarter within group
    {
        float acc[4][4][4];
        #pragma unroll
        for (int mt = 0; mt < 4; mt++)
            #pragma unroll
            for (int nt = 0; nt < 4; nt++)
                #pragma unroll
                for (int i = 0; i < 4; i++) acc[mt][nt][i] = 0.f;
        const int nb = w4 * 32;
        const float* bW1 = sW1 + bl * W1S + bn + nb;
        #pragma unroll
        for (int k8 = 0; k8 < 16; k8++) {
            uint32_t a[4][4], b[4][2];
            #pragma unroll
            for (int mt = 0; mt < 4; mt++)
                ldsm4(a[mt], uAct + 4u * ((g2 * 64 + mt * 16) * SST + k8 * 8) + aoffT);
            const float* bp = bW1 + k8 * 8 * W1S;
            #pragma unroll
            for (int nt = 0; nt < 4; nt++) {
                b[nt][0] = __float_as_uint(bp[nt * 8]);
                b[nt][1] = __float_as_uint(bp[nt * 8 + 4 * W1S]);
            }
            #pragma unroll
            for (int mt = 0; mt < 4; mt++)
                #pragma unroll
                for (int nt = 0; nt < 4; nt++)
                    mma8(acc[mt][nt], a[mt], b[nt]);
        }
        BAR_G(g2);          // group's reads of its rows done before h1 overwrites them
        const int r0b = g2 * 64 + (l >> 2);
        const int cb  = nb + 2 * (l & 3);
        #pragma unroll
        for (int mt = 0; mt < 4; mt++)
            #pragma unroll
            for (int nt = 0; nt < 4; nt++) {
                int c = cb + nt * 8;
                float bb0 = sB1[c], bb1 = sB1[c + 1];
                int r0 = r0b + mt * 16;
                float2 v0, v1;
                v0.x = fmaxf(acc[mt][nt][0] + bb0, 0.f);
                v0.y = fmaxf(acc[mt][nt][1] + bb1, 0.f);
                v1.x = fmaxf(acc[mt][nt][2] + bb0, 0.f);
                v1.y = fmaxf(acc[mt][nt][3] + bb1, 0.f);
                *(float2*)&sAct[r0 * SST + c] = v0;
                *(float2*)&sAct[(r0 + 8) * SST + c] = v1;
            }
    }
    CP_WAIT(0);          // W2 landed (own copies)
    __syncthreads();     // W2 visible block-wide (staged by all threads) + h1 visible

    // ============ GEMM2: per group rows 64, warps = 2M x 2N (32x32 tiles) + fused 64->1 ============
    {
        const int mh = w4 & 1, nh = w4 >> 1;
        float acc[2][4][4];
        #pragma unroll
        for (int mt = 0; mt < 2; mt++)
            #pragma unroll
            for (int nt = 0; nt < 4; nt++)
                #pragma unroll
                for (int i = 0; i < 4; i++) acc[mt][nt][i] = 0.f;
        const int nb2 = nh * 32;
        const int rowb = g2 * 64 + mh * 32;
        const float* bW2 = sW2 + bl * WUS + bn + nb2;
        #pragma unroll
        for (int k8 = 0; k8 < 16; k8++) {
            uint32_t a[2][4], b[4][2];
            #pragma unroll
            for (int mt = 0; mt < 2; mt++)
                ldsm4(a[mt], uAct + 4u * ((rowb + mt * 16) * SST + k8 * 8) + aoffT);
            const float* bp = bW2 + k8 * 8 * WUS;
            #pragma unroll
            for (int nt = 0; nt < 4; nt++) {
                b[nt][0] = __float_as_uint(bp[nt * 8]);
                b[nt][1] = __float_as_uint(bp[nt * 8 + 4 * WUS]);
            }
            #pragma unroll
            for (int mt = 0; mt < 2; mt++)
                #pragma unroll
                for (int nt = 0; nt < 4; nt++)
                    mma8(acc[mt][nt], a[mt], b[nt]);
        }
        // fused: p[row] += relu(h2+b2)*w3, reduce over 4-lane col groups, atomic into sOut
        const int cb = nb2 + 2 * (l & 3);
        float part[2][2];
        part[0][0] = part[0][1] = part[1][0] = part[1][1] = 0.f;
        #pragma unroll
        for (int nt = 0; nt < 4; nt++) {
            int c = cb + nt * 8;
            float bb0 = sB2[c], bb1 = sB2[c + 1];
            float w30 = sW3[c], w31 = sW3[c + 1];
            #pragma unroll
            for (int mt = 0; mt < 2; mt++) {
                part[mt][0] = fmaf(fmaxf(acc[mt][nt][0] + bb0, 0.f), w30,
                              fmaf(fmaxf(acc[mt][nt][1] + bb1, 0.f), w31, part[mt][0]));
                part[mt][1] = fmaf(fmaxf(acc[mt][nt][2] + bb0, 0.f), w30,
                              fmaf(fmaxf(acc[mt][nt][3] + bb1, 0.f), w31, part[mt][1]));
            }
        }
        #pragma unroll
        for (int mt = 0; mt < 2; mt++)
            #pragma unroll
            for (int rh = 0; rh < 2; rh++) {
                part[mt][rh] += __shfl_xor_sync(0xffffffffu, part[mt][rh], 1);
                part[mt][rh] += __shfl_xor_sync(0xffffffffu, part[mt][rh], 2);
            }
        if ((l & 3) == 0) {
            const int r0b = rowb + (l >> 2);
            #pragma unroll
            for (int mt = 0; mt < 2; mt++) {
                atomicAdd(&sOut[r0b + mt * 16],     part[mt][0]);
                atomicAdd(&sOut[r0b + mt * 16 + 8], part[mt][1]);
            }
        }
    }
    BAR_G(g2);           // group's sOut rows complete

    // ============ output (group-local rows) ============
    {
        const int gt = t & 127;
        if (gt < 64) {
            const int r = g2 * 64 + gt;
            out[base + r] = fmaxf(sOut[r] + __ldg(b3), 0.f);
        }
    }
}

extern "C" void kernel_launch(void* const* d_in, const int* in_sizes, int n_in,
                              void* d_out, int out_size)
{
    const int*   user_id    = (const int*)d_in[0];
    const int*   item_id    = (const int*)d_in[1];
    const float* rec_target = (const float*)d_in[2];
    const float* user_emb   = (const float*)d_in[3];
    const float* item_emb   = (const float*)d_in[4];
    const float* entity_emb = (const float*)d_in[5];
    const float* w_vv = (const float*)d_in[6];
    const float* w_ev = (const float*)d_in[7];
    const float* w_ve = (const float*)d_in[8];
    const float* w_ee = (const float*)d_in[9];
    const float* b_v  = (const float*)d_in[10];
    const float* b_e  = (const float*)d_in[11];
    const float* Wul  = (const float*)d_in[12];
    const float* bul  = (const float*)d_in[13];
    const float* W1   = (const float*)d_in[14];
    const float* b1   = (const float*)d_in[15];
    const float* W2   = (const float*)d_in[16];
    const float* b2   = (const float*)d_in[17];
    const float* W3   = (const float*)d_in[18];
    const float* b3   = (const float*)d_in[19];

    cudaFuncSetAttribute(multikr_mma_kernel,
                         cudaFuncAttributeMaxDynamicSharedMemorySize, SMEM_BYTES);

    const int n = in_sizes[0];      // 16384
    const int nblk = n / 128;       // 128 blocks, one wave
    multikr_mma_kernel<<<nblk, NT, SMEM_BYTES>>>(
        user_id, item_id, rec_target, user_emb, item_emb, entity_emb,
        w_vv, w_ev, w_ve, w_ee, b_v, b_e, Wul, bul,
        W1, b1, W2, b2, W3, b3,
        (float*)d_out, out_size);
}